// round 2
// baseline (speedup 1.0000x reference)
#include <cuda_runtime.h>

// ---------------- problem constants ----------------
#define BS    256
#define SEQ   4096
#define DD    128
#define NCATS 256
#define GCOLS 384              // 3*D combined gate columns [hr | hz | hn]

typedef unsigned long long u64;

// ---------------- device scratch (no allocations allowed) ----------------
__device__ float g_H[(size_t)BS * SEQ * DD];     // 512 MB hidden-state history
__device__ float g_proj[257 * GCOLS];            // per-token input projection table
__device__ int   g_is64;                         // 1 if x is int64, 0 if int32

// ---------------- f32x2 packed helpers (sm_103a FFMA2 path) ----------------
__device__ __forceinline__ u64 f2_dup(float v) {
    u64 r; asm("mov.b64 %0, {%1, %1};" : "=l"(r) : "f"(v)); return r;
}
__device__ __forceinline__ void f2_fma(u64& acc, u64 a, u64 b) {
    asm("fma.rn.f32x2 %0, %1, %2, %0;" : "+l"(acc) : "l"(a), "l"(b));
}
__device__ __forceinline__ float2 f2_unpack(u64 v) {
    float lo, hi; asm("mov.b64 {%0, %1}, %2;" : "=f"(lo), "=f"(hi) : "l"(v));
    return make_float2(lo, hi);
}

// ---------------- kernel 1: int64/int32 detection ----------------
// If x is int64 (values < 2^31), every odd 32-bit word of the buffer is 0.
// If x is int32, odd words are random tokens in [0,256) -> virtually surely nonzero.
__global__ void detect_kernel(const unsigned int* xw) {
    __shared__ unsigned int s[256];
    unsigned int v = 0;
    for (int i = threadIdx.x; i < 4096; i += 256) v |= xw[2 * i + 1];
    s[threadIdx.x] = v;
    __syncthreads();
    if (threadIdx.x == 0) {
        unsigned int a = 0;
        for (int i = 0; i < 256; i++) a |= s[i];
        g_is64 = (a == 0) ? 1 : 0;
    }
}

// ---------------- kernel 2: proj[c] = embed[c] @ Wi + bi  (257 x 384) ----------------
__global__ void __launch_bounds__(GCOLS) proj_kernel(const float* __restrict__ emb,
                                                     const float* __restrict__ Wi,
                                                     const float* __restrict__ bi) {
    __shared__ float e[DD];
    const int c = blockIdx.x;
    const int j = threadIdx.x;
    if (j < DD) e[j] = emb[c * DD + j];
    __syncthreads();
    float acc = bi[j];
#pragma unroll 8
    for (int k = 0; k < DD; k++) acc += e[k] * Wi[k * GCOLS + j];
    g_proj[c * GCOLS + j] = acc;
}

// ---------------- kernel 3: GRU scan, 128 CTAs x 2 batch rows ----------------
// smem: Ws[128][384] fp32 combined recurrent weights (192 KB)
//       h2s[128] float2 (rowA,rowB hidden state, interleaved)
//       gbuf[384] float2 (matvec results), xib[384] float2 (gathered xi)
__global__ void __launch_bounds__(GCOLS, 1) scan_kernel(const int* __restrict__ xw,
                                                        const float* __restrict__ Whrz,
                                                        const float* __restrict__ Whn,
                                                        const float* __restrict__ bhn,
                                                        const float* __restrict__ initst) {
    extern __shared__ float sm[];
    float*  Ws   = sm;                               // 49152 floats
    float2* h2s  = (float2*)(sm + DD * GCOLS);       // 128 float2
    float2* gbuf = h2s + DD;                         // 384 float2
    float2* xib  = gbuf + GCOLS;                     // 384 float2
    __shared__ int s_tok[2];

    const int j  = threadIdx.x;
    const int rA = blockIdx.x * 2;
    const int rB = rA + 1;

    // stage combined recurrent weight matrix [k][j]: j<256 -> Wh_rz, else Wh_n
    for (int k = 0; k < DD; k++) {
        float w = (j < 256) ? Whrz[k * 256 + j] : Whn[k * DD + (j - 256)];
        Ws[k * GCOLS + j] = w;
    }
    const int is64 = g_is64;

    float2 hold = make_float2(0.f, 0.f);
    float  bn   = 0.f;
    if (j < DD) {
        float v = initst[j];
        hold = make_float2(v, v);
        h2s[j] = hold;
        bn = bhn[j];
    }
    if (j == 0) { s_tok[0] = NCATS; s_tok[1] = NCATS; }   // BOS at t=0
    __syncthreads();

    for (int t = 0; t < SEQ; t++) {
        // gather xi for both rows (L2-resident proj table); hides behind matvec
        const int tA = s_tok[0], tB = s_tok[1];
        const float xiA = g_proj[tA * GCOLS + j];
        const float xiB = g_proj[tB * GCOLS + j];

        // matvec: column j of h @ [Wh_rz | Wh_n] for both rows via f32x2
        u64 acc = 0ull;
        const float* wk = Ws + j;
        const ulonglong2* hp = (const ulonglong2*)h2s;   // (h pair for k, k+1)
#pragma unroll 16
        for (int k2 = 0; k2 < 64; k2++) {
            ulonglong2 hh = hp[k2];                      // h2s[2k2], h2s[2k2+1]
            float w0 = wk[0];
            float w1 = wk[GCOLS];
            wk += 2 * GCOLS;
            f2_fma(acc, hh.x, f2_dup(w0));
            f2_fma(acc, hh.y, f2_dup(w1));
        }
        gbuf[j] = f2_unpack(acc);
        xib[j]  = make_float2(xiA, xiB);
        __syncthreads();

        if (j < DD) {
            float2 hr = gbuf[j], hz = gbuf[DD + j], hn = gbuf[2 * DD + j];
            float2 xr = xib[j],  xz = xib[DD + j],  xn = xib[2 * DD + j];

            float r0 = 1.f / (1.f + __expf(-(xr.x + hr.x)));
            float z0 = 1.f / (1.f + __expf(-(xz.x + hz.x)));
            float n0 = tanhf(xn.x + r0 * (hn.x + bn));
            float h0 = (1.f - z0) * n0 + z0 * hold.x;

            float r1 = 1.f / (1.f + __expf(-(xr.y + hr.y)));
            float z1 = 1.f / (1.f + __expf(-(xz.y + hz.y)));
            float n1 = tanhf(xn.y + r1 * (hn.y + bn));
            float h1 = (1.f - z1) * n1 + z1 * hold.y;

            hold = make_float2(h0, h1);
            h2s[j] = hold;
            g_H[((size_t)rA * SEQ + t) * DD + j] = h0;
            g_H[((size_t)rB * SEQ + t) * DD + j] = h1;
        } else if (j == 128 || j == 129) {
            // prefetch tokens_in[t+1] = x[row][t]
            if (t + 1 < SEQ) {
                int row = (j == 128) ? rA : rB;
                int idx = row * SEQ + t;
                s_tok[j - 128] = is64 ? xw[2 * idx] : xw[idx];
            }
        }
        __syncthreads();
    }
}

// ---------------- kernel 4: logits = H @ W_cls + b_cls ----------------
// grid (32, 256): block = (row, 128-timestep tile). 512 threads, 8x8 microtile, f32x2.
#define HS_STRIDE 132   // padded transposed-H row stride (16B-aligned, STS conflicts only in load phase)
__global__ void __launch_bounds__(512, 1) logits_kernel(const float* __restrict__ Wcls,
                                                        const float* __restrict__ bcls,
                                                        float* __restrict__ out) {
    extern __shared__ float sm[];
    float* Wc = sm;                    // [128][256]
    float* Hs = sm + DD * 256;         // [128][HS_STRIDE] transposed H tile (d, r)
    const int tid = threadIdx.x;
    const int row = blockIdx.y;
    const int t0  = blockIdx.x * 128;

    for (int i = tid; i < DD * 256; i += 512) Wc[i] = Wcls[i];
    for (int rr = 0; rr < 128; rr += 4) {
        int r = rr + (tid >> 7);
        int d = tid & 127;
        Hs[d * HS_STRIDE + r] = g_H[((size_t)row * SEQ + t0 + r) * DD + d];
    }
    __syncthreads();

    const int tc = tid & 31;           // 32 col groups of 8
    const int tr = tid >> 5;           // 16 row groups of 8
    const int c0 = tc * 8, r0 = tr * 8;

    float bc[8];
#pragma unroll
    for (int cc = 0; cc < 8; cc++) bc[cc] = bcls[c0 + cc];

    u64 acc[8][4];
#pragma unroll
    for (int a = 0; a < 8; a++)
#pragma unroll
        for (int b = 0; b < 4; b++) acc[a][b] = 0ull;

#pragma unroll 4
    for (int d = 0; d < DD; d++) {
        float4 hA = *(const float4*)&Hs[d * HS_STRIDE + r0];       // broadcast within warp
        float4 hB = *(const float4*)&Hs[d * HS_STRIDE + r0 + 4];
        ulonglong2 wA = *(const ulonglong2*)&Wc[d * 256 + c0];     // 4 cols
        ulonglong2 wB = *(const ulonglong2*)&Wc[d * 256 + c0 + 4]; // 4 cols
        float hv[8] = {hA.x, hA.y, hA.z, hA.w, hB.x, hB.y, hB.z, hB.w};
#pragma unroll
        for (int a = 0; a < 8; a++) {
            u64 h2 = f2_dup(hv[a]);
            f2_fma(acc[a][0], h2, wA.x);
            f2_fma(acc[a][1], h2, wA.y);
            f2_fma(acc[a][2], h2, wB.x);
            f2_fma(acc[a][3], h2, wB.y);
        }
    }

#pragma unroll
    for (int a = 0; a < 8; a++) {
        float2 p0 = f2_unpack(acc[a][0]);
        float2 p1 = f2_unpack(acc[a][1]);
        float2 p2 = f2_unpack(acc[a][2]);
        float2 p3 = f2_unpack(acc[a][3]);
        float4 o1 = make_float4(p0.x + bc[0], p0.y + bc[1], p1.x + bc[2], p1.y + bc[3]);
        float4 o2 = make_float4(p2.x + bc[4], p2.y + bc[5], p3.x + bc[6], p3.y + bc[7]);
        size_t base = ((size_t)row * SEQ + t0 + r0 + a) * 256 + c0;
        *(float4*)&out[base]     = o1;
        *(float4*)&out[base + 4] = o2;
    }
}

// ---------------- launch ----------------
extern "C" void kernel_launch(void* const* d_in, const int* in_sizes, int n_in,
                              void* d_out, int out_size) {
    const void*  x      = d_in[0];
    const float* emb    = (const float*)d_in[1];
    const float* Wi     = (const float*)d_in[2];
    const float* bi     = (const float*)d_in[3];
    const float* Whrz   = (const float*)d_in[4];
    const float* Whn    = (const float*)d_in[5];
    const float* bhn    = (const float*)d_in[6];
    const float* Wcls   = (const float*)d_in[7];
    const float* bcls   = (const float*)d_in[8];
    const float* initst = (const float*)d_in[9];
    float* out = (float*)d_out;

    const int SCAN_SMEM = (DD * GCOLS + 2 * DD + 4 * GCOLS) * (int)sizeof(float);     // 203,776 B
    const int LOG_SMEM  = (DD * 256 + DD * HS_STRIDE) * (int)sizeof(float);           // 198,656 B
    cudaFuncSetAttribute(scan_kernel,   cudaFuncAttributeMaxDynamicSharedMemorySize, SCAN_SMEM);
    cudaFuncSetAttribute(logits_kernel, cudaFuncAttributeMaxDynamicSharedMemorySize, LOG_SMEM);

    detect_kernel<<<1, 256>>>((const unsigned int*)x);
    proj_kernel<<<257, GCOLS>>>(emb, Wi, bi);
    scan_kernel<<<BS / 2, GCOLS, SCAN_SMEM>>>((const int*)x, Whrz, Whn, bhn, initst);
    logits_kernel<<<dim3(SEQ / 128, BS), 512, LOG_SMEM>>>(Wcls, bcls, out);
}

// round 6
// speedup vs baseline: 3.7438x; 3.7438x over previous
#include <cuda_runtime.h>
#include <cuda_fp16.h>
#include <stdint.h>

// ---------------- problem constants ----------------
#define BS    256
#define SEQ   4096
#define DD    128
#define NCATS 256
#define GCOLS 384

// ---------------- device scratch ----------------
__device__ __half g_Hh[(size_t)BS * SEQ * DD];   // hidden history, fp16 (for logits GEMM)
__device__ float  g_proj4[257 * DD * 4];         // per-token xi: [tok][d][{xr,xz,xn,0}]
__device__ __half g_WcT[NCATS * DD];             // W_cls transposed -> [cat][d], fp16
__device__ int    g_is64;

// ---------------- helpers ----------------
__device__ __forceinline__ uint32_t smem_u32(const void* p) {
    uint32_t a;
    asm("{ .reg .u64 t; cvta.to.shared.u64 t, %1; cvt.u32.u64 %0, t; }" : "=r"(a) : "l"(p));
    return a;
}
__device__ __forceinline__ uint32_t packh2(float a, float b) {
    __half2 h = __floats2half2_rn(a, b);
    return *reinterpret_cast<uint32_t*>(&h);
}
__device__ __forceinline__ void mma16816(float* d, const uint32_t* a, const uint32_t* b) {
    asm volatile(
        "mma.sync.aligned.m16n8k16.row.col.f32.f16.f16.f32 "
        "{%0,%1,%2,%3}, {%4,%5,%6,%7}, {%8,%9}, {%0,%1,%2,%3};\n"
        : "+f"(d[0]), "+f"(d[1]), "+f"(d[2]), "+f"(d[3])
        : "r"(a[0]), "r"(a[1]), "r"(a[2]), "r"(a[3]), "r"(b[0]), "r"(b[1]));
}
__device__ __forceinline__ void ldsm_x4(uint32_t* r, uint32_t addr) {
    asm volatile("ldmatrix.sync.aligned.m8n8.x4.shared.b16 {%0,%1,%2,%3}, [%4];"
                 : "=r"(r[0]), "=r"(r[1]), "=r"(r[2]), "=r"(r[3]) : "r"(addr));
}
__device__ __forceinline__ float ex2f(float x) {
    float y; asm("ex2.approx.f32 %0, %1;" : "=f"(y) : "f"(x)); return y;
}
__device__ __forceinline__ float rcpf(float x) {
    float y; asm("rcp.approx.f32 %0, %1;" : "=f"(y) : "f"(x)); return y;
}
__device__ __forceinline__ float sigf(float x) {
    return rcpf(1.f + ex2f(-1.4426950408889634f * x));
}
__device__ __forceinline__ float tanhf_fast(float x) {
    return 1.f - 2.f * rcpf(1.f + ex2f(2.8853900817779268f * x));
}

// ---------------- kernel 1: int64/int32 detection ----------------
__global__ void detect_kernel(const unsigned int* xw) {
    __shared__ unsigned int s[256];
    unsigned int v = 0;
    for (int i = threadIdx.x; i < 4096; i += 256) v |= xw[2 * i + 1];
    s[threadIdx.x] = v;
    __syncthreads();
    if (threadIdx.x == 0) {
        unsigned int a = 0;
        for (int i = 0; i < 256; i++) a |= s[i];
        g_is64 = (a == 0) ? 1 : 0;
    }
}

// ---------------- kernel 2: proj4[c][d] = (xr, xz, xn, 0) ----------------
__global__ void __launch_bounds__(DD) proj_kernel(const float* __restrict__ emb,
                                                  const float* __restrict__ Wi,
                                                  const float* __restrict__ bi) {
    __shared__ float e[DD];
    const int c = blockIdx.x;
    const int j = threadIdx.x;
    e[j] = emb[c * DD + j];
    __syncthreads();
    float a0 = bi[j], a1 = bi[DD + j], a2 = bi[2 * DD + j];
#pragma unroll 8
    for (int k = 0; k < DD; k++) {
        float ek = e[k];
        a0 += ek * Wi[k * GCOLS + j];
        a1 += ek * Wi[k * GCOLS + DD + j];
        a2 += ek * Wi[k * GCOLS + 2 * DD + j];
    }
    float4* o = (float4*)&g_proj4[(size_t)(c * DD + j) * 4];
    *o = make_float4(a0, a1, a2, 0.f);
}

// ---------------- kernel 2b: W_cls -> fp16 transposed ----------------
__global__ void prep_wc(const float* __restrict__ Wcls) {
    int i = blockIdx.x * 256 + threadIdx.x;      // 32768
    int d = i / NCATS, c = i % NCATS;
    g_WcT[c * DD + d] = __float2half_rn(Wcls[d * NCATS + c]);
}

// ---------------- kernel 3: HMMA GRU scan, 128 CTAs x 2 rows ----------------
// Weights live in registers as mma A-fragments (fp16). 8 warps x 3 M-tiles of 16 gates.
#define HTP 136   // padded hT row (halves) -> 272B stride, conflict-free
__global__ void __launch_bounds__(256, 1)
scan_kernel(const int* __restrict__ xw,
            const float* __restrict__ Whrz,
            const float* __restrict__ Whn,
            const float* __restrict__ bhn,
            const float* __restrict__ initst) {
    __shared__ __half hT[8][HTP];       // B operand: [n][k], rows 2..7 stay zero
    __shared__ float  gbuf[GCOLS][2];   // MMA results [gate][row]

    const int tid = threadIdx.x;
    const int w = tid >> 5, l = tid & 31;
    const int row0 = blockIdx.x * 2;
    const int d = tid & 127, r = tid >> 7;    // gate-phase mapping (1 set/thread)

    // ---- build A fragments in registers: G[g][k] = W[k][g], fp16 ----
    uint32_t A[3][8][4];
    {
        const int gr = l >> 2;             // 0..7
        const int kc = (l & 3) * 2;        // 0,2,4,6
#pragma unroll
        for (int s = 0; s < 3; s++) {
            const int g0 = (w * 3 + s) * 16;
#pragma unroll
            for (int kt = 0; kt < 8; kt++) {
                const int k0 = kt * 16 + kc;
                int ga = g0 + gr, gb = g0 + gr + 8;
                float a00, a01, a10, a11, a20, a21, a30, a31;
                if (ga < 256) { a00 = Whrz[k0 * 256 + ga];       a01 = Whrz[(k0 + 1) * 256 + ga];
                                a20 = Whrz[(k0 + 8) * 256 + ga]; a21 = Whrz[(k0 + 9) * 256 + ga]; }
                else          { int gg = ga - 256;
                                a00 = Whn[k0 * DD + gg];         a01 = Whn[(k0 + 1) * DD + gg];
                                a20 = Whn[(k0 + 8) * DD + gg];   a21 = Whn[(k0 + 9) * DD + gg]; }
                if (gb < 256) { a10 = Whrz[k0 * 256 + gb];       a11 = Whrz[(k0 + 1) * 256 + gb];
                                a30 = Whrz[(k0 + 8) * 256 + gb]; a31 = Whrz[(k0 + 9) * 256 + gb]; }
                else          { int gg = gb - 256;
                                a10 = Whn[k0 * DD + gg];         a11 = Whn[(k0 + 1) * DD + gg];
                                a30 = Whn[(k0 + 8) * DD + gg];   a31 = Whn[(k0 + 9) * DD + gg]; }
                A[s][kt][0] = packh2(a00, a01);
                A[s][kt][1] = packh2(a10, a11);
                A[s][kt][2] = packh2(a20, a21);
                A[s][kt][3] = packh2(a30, a31);
            }
        }
    }

    // ---- init hT (zero padding rows), h, xi(BOS), first token ----
    for (int i = tid; i < 8 * HTP; i += 256) ((__half*)hT)[i] = __float2half(0.f);
    __syncthreads();
    float h = initst[d];
    const float bn = bhn[d];
    hT[r][d] = __float2half_rn(h);
    float4 xi = *(const float4*)&g_proj4[(size_t)(NCATS * DD + d) * 4];   // BOS
    const int is64 = g_is64;
    const int xbase = (row0 + r) * SEQ;
    int tok = is64 ? xw[2 * xbase] : xw[xbase];

    const uint32_t bRow = (uint32_t)((l >> 2) * HTP * 2);   // byte offset of this lane's B row
    const uint32_t bCol = (uint32_t)((l & 3) * 4);          // 2 halves

    for (int t = 0; t < SEQ; t++) {
        __syncthreads();   // hT(t) ready

        // ---- MMA phase: D[384x2] = G @ h ----
        float acc[3][4];
#pragma unroll
        for (int s = 0; s < 3; s++)
#pragma unroll
            for (int q = 0; q < 4; q++) acc[s][q] = 0.f;

        const char* hbase = (const char*)hT + bRow + bCol;
#pragma unroll
        for (int kt = 0; kt < 8; kt++) {
            uint32_t b[2];
            b[0] = *(const uint32_t*)(hbase + kt * 32);
            b[1] = *(const uint32_t*)(hbase + kt * 32 + 16);
#pragma unroll
            for (int s = 0; s < 3; s++) mma16816(acc[s], A[s][kt], b);
        }
        if ((l & 3) == 0) {
            const int gr = l >> 2;
#pragma unroll
            for (int s = 0; s < 3; s++) {
                const int g = (w * 3 + s) * 16 + gr;
                *(float2*)&gbuf[g][0]     = make_float2(acc[s][0], acc[s][1]);
                *(float2*)&gbuf[g + 8][0] = make_float2(acc[s][2], acc[s][3]);
            }
        }
        __syncthreads();

        // ---- gates: one (d, row) pair per thread ----
        float hr = gbuf[d][r], hz = gbuf[DD + d][r], hnp = gbuf[2 * DD + d][r];

        // prefetch next xi / token (overlaps with MUFU chain)
        float4 xin = *(const float4*)&g_proj4[(size_t)(tok * DD + d) * 4];
        int tokn = tok;
        if (t + 1 < SEQ) {
            int idx = xbase + t + 1;
            tokn = is64 ? xw[2 * idx] : xw[idx];
        }

        float R = sigf(xi.x + hr);
        float Z = sigf(xi.y + hz);
        float N = tanhf_fast(xi.z + R * (hnp + bn));
        h = N + Z * (h - N);

        g_Hh[((size_t)(row0 + r) * SEQ + t) * DD + d] = __float2half_rn(h);
        hT[r][d] = __float2half_rn(h);
        xi = xin; tok = tokn;
    }
}

// ---------------- kernel 4: logits = H @ W_cls + b_cls via HMMA ----------------
// per CTA: 128 timesteps x 256 cats, K=128. 8 warps = 2x4 tiling, 64x64 each.
#define HPAD 136
__global__ void __launch_bounds__(256, 1) logits_kernel(const float* __restrict__ bcls,
                                                        float* __restrict__ out) {
    extern __shared__ __half sh[];
    __half* Hs = sh;                    // [128][HPAD]
    __half* Wc = sh + 128 * HPAD;       // [256][HPAD]  (WcT: [cat][d])
    const int tid = threadIdx.x;
    const int batch = blockIdx.y;
    const int t0 = blockIdx.x * 128;

    const __half* hsrc = &g_Hh[((size_t)batch * SEQ + t0) * DD];
    for (int i = tid; i < 128 * 16; i += 256) {
        int rr = i >> 4, c8 = (i & 15) * 8;
        *(float4*)&Hs[rr * HPAD + c8] = *(const float4*)&hsrc[rr * DD + c8];
    }
    for (int i = tid; i < 256 * 16; i += 256) {
        int rr = i >> 4, c8 = (i & 15) * 8;
        *(float4*)&Wc[rr * HPAD + c8] = *(const float4*)&g_WcT[rr * DD + c8];
    }
    __syncthreads();

    const int w = tid >> 5, l = tid & 31;
    const int m0 = (w >> 2) * 64;       // 2 m-groups
    const int n0 = (w & 3) * 64;        // 4 n-groups

    float acc[4][8][4];
#pragma unroll
    for (int nt = 0; nt < 8; nt++) {
        float b0 = bcls[n0 + nt * 8 + (l & 3) * 2];
        float b1 = bcls[n0 + nt * 8 + (l & 3) * 2 + 1];
#pragma unroll
        for (int mt = 0; mt < 4; mt++) {
            acc[mt][nt][0] = b0; acc[mt][nt][1] = b1;
            acc[mt][nt][2] = b0; acc[mt][nt][3] = b1;
        }
    }

    const uint32_t hs_u32 = smem_u32(Hs);
    const int arow = m0 + (l & 15);
    const int acol = (l >> 4) * 8;
#pragma unroll
    for (int kt = 0; kt < 8; kt++) {
        uint32_t Af[4][4];
#pragma unroll
        for (int mt = 0; mt < 4; mt++)
            ldsm_x4(Af[mt], hs_u32 + (uint32_t)(((arow + mt * 16) * HPAD + kt * 16 + acol) * 2));
        uint32_t Bf[8][2];
#pragma unroll
        for (int nt = 0; nt < 8; nt++) {
            const __half* wp = &Wc[(n0 + nt * 8 + (l >> 2)) * HPAD + kt * 16 + (l & 3) * 2];
            Bf[nt][0] = *(const uint32_t*)wp;
            Bf[nt][1] = *(const uint32_t*)(wp + 8);
        }
#pragma unroll
        for (int mt = 0; mt < 4; mt++)
#pragma unroll
            for (int nt = 0; nt < 8; nt++) mma16816(acc[mt][nt], Af[mt], Bf[nt]);
    }

    const size_t obase = ((size_t)batch * SEQ + t0) * NCATS;
#pragma unroll
    for (int mt = 0; mt < 4; mt++) {
        const int row = m0 + mt * 16 + (l >> 2);
#pragma unroll
        for (int nt = 0; nt < 8; nt++) {
            const int col = n0 + nt * 8 + (l & 3) * 2;
            *(float2*)&out[obase + (size_t)row * NCATS + col] =
                make_float2(acc[mt][nt][0], acc[mt][nt][1]);
            *(float2*)&out[obase + (size_t)(row + 8) * NCATS + col] =
                make_float2(acc[mt][nt][2], acc[mt][nt][3]);
        }
    }
}

// ---------------- launch ----------------
extern "C" void kernel_launch(void* const* d_in, const int* in_sizes, int n_in,
                              void* d_out, int out_size) {
    const void*  x      = d_in[0];
    const float* emb    = (const float*)d_in[1];
    const float* Wi     = (const float*)d_in[2];
    const float* bi     = (const float*)d_in[3];
    const float* Whrz   = (const float*)d_in[4];
    const float* Whn    = (const float*)d_in[5];
    const float* bhn    = (const float*)d_in[6];
    const float* Wcls   = (const float*)d_in[7];
    const float* bcls   = (const float*)d_in[8];
    const float* initst = (const float*)d_in[9];
    float* out = (float*)d_out;

    const int LOG_SMEM = (128 + 256) * HPAD * (int)sizeof(__half);   // 104448 B
    cudaFuncSetAttribute(logits_kernel, cudaFuncAttributeMaxDynamicSharedMemorySize, LOG_SMEM);

    detect_kernel<<<1, 256>>>((const unsigned int*)x);
    proj_kernel<<<257, DD>>>(emb, Wi, bi);
    prep_wc<<<(NCATS * DD) / 256, 256>>>(Wcls);
    scan_kernel<<<BS / 2, 256>>>((const int*)x, Whrz, Whn, bhn, initst);
    logits_kernel<<<dim3(SEQ / 128, BS), 256, LOG_SMEM>>>(bcls, out);
}